// round 7
// baseline (speedup 1.0000x reference)
#include <cuda_runtime.h>
#include <cuda_bf16.h>

// DistMult edge scoring:
//   out[r, e] = sigmoid( sum_d h[src[r,e], d] * W[r, d] * h[dst[r,e], d] )
// h [100000,128] f32, W [6,128] f32, src/dst [6,200000] int32, out [6,200000] f32.
//
// R7: occupancy push. R6 was latency-exposed (L2=74%, L1=62%, occ=45.6%)
// with regs=64 capping the SM at 4 CTAs. Move W (512B) and the 5x32
// per-block index pairs into shared memory (broadcast LDS reads), cap regs
// at 51 via __launch_bounds__(256,5) -> 40 warps/SM (+25%), while keeping
// the 8x LDG.128 row burst (MLP=8) per phase.

#define N_HID 128
#define E_PER_REL 200000
#define N_REL 6
#define BLOCK 256
#define EDGES_PER_BLOCK 32      // 256 threads / 8 lanes per edge
#define GRID_X 1250             // 1250 * 32 * 5 == 200000 exactly
#define ITERS 5
#define STRIDE (GRID_X * EDGES_PER_BLOCK)   // 40000

__global__ __launch_bounds__(BLOCK, 5)
void distmult_kernel(const float4* __restrict__ h4,
                     const float4* __restrict__ W4,
                     const int* __restrict__ src_idx,
                     const int* __restrict__ dst_idx,
                     float* __restrict__ out) {
    __shared__ float4 Wsh[N_HID / 4];                 // 512 B, this block's relation
    __shared__ int    Sidx[ITERS * EDGES_PER_BLOCK];  // 160 ints
    __shared__ int    Didx[ITERS * EDGES_PER_BLOCK];  // 160 ints

    const int rel   = blockIdx.y;
    const int tid   = threadIdx.x;
    const int sub   = tid & 7;     // lane within 8-lane edge group
    const int group = tid >> 3;    // edge slot within block: 0..31

    const int* __restrict__ srcR = src_idx + rel * E_PER_REL;
    const int* __restrict__ dstR = dst_idx + rel * E_PER_REL;
    float* __restrict__ outR = out + rel * E_PER_REL;

    // Prologue: W row (32 threads x float4) + all phase indices, coalesced.
    if (tid < N_HID / 4)
        Wsh[tid] = __ldg(W4 + rel * (N_HID / 4) + tid);
    if (tid < ITERS * EDGES_PER_BLOCK) {
        const int i = tid >> 5;          // phase
        const int g = tid & 31;          // group slot
        const int e = blockIdx.x * EDGES_PER_BLOCK + i * STRIDE + g;
        Sidx[tid] = __ldg(srcR + e);
        Didx[tid] = __ldg(dstR + e);
    }
    __syncthreads();

    const int e0 = blockIdx.x * EDGES_PER_BLOCK + group;

    #pragma unroll
    for (int i = 0; i < ITERS; i++) {
        const int s = Sidx[i * EDGES_PER_BLOCK + group];   // LDS broadcast
        const int d = Didx[i * EDGES_PER_BLOCK + group];

        const float4* __restrict__ hs = h4 + (long long)s * (N_HID / 4);
        const float4* __restrict__ hd = h4 + (long long)d * (N_HID / 4);

        // 8 independent 16B loads in flight per thread.
        float4 a0 = __ldg(hs + sub);
        float4 a1 = __ldg(hs + sub + 8);
        float4 a2 = __ldg(hs + sub + 16);
        float4 a3 = __ldg(hs + sub + 24);
        float4 b0 = __ldg(hd + sub);
        float4 b1 = __ldg(hd + sub + 8);
        float4 b2 = __ldg(hd + sub + 16);
        float4 b3 = __ldg(hd + sub + 24);

        // W chunks from smem: broadcast across the 4 groups (same addr per sub).
        const float4 w0 = Wsh[sub];
        const float4 w1 = Wsh[sub + 8];
        const float4 w2 = Wsh[sub + 16];
        const float4 w3 = Wsh[sub + 24];

        float acc;
        acc = a0.x * w0.x * b0.x;
        acc = fmaf(a0.y * w0.y, b0.y, acc);
        acc = fmaf(a0.z * w0.z, b0.z, acc);
        acc = fmaf(a0.w * w0.w, b0.w, acc);
        acc = fmaf(a1.x * w1.x, b1.x, acc);
        acc = fmaf(a1.y * w1.y, b1.y, acc);
        acc = fmaf(a1.z * w1.z, b1.z, acc);
        acc = fmaf(a1.w * w1.w, b1.w, acc);
        acc = fmaf(a2.x * w2.x, b2.x, acc);
        acc = fmaf(a2.y * w2.y, b2.y, acc);
        acc = fmaf(a2.z * w2.z, b2.z, acc);
        acc = fmaf(a2.w * w2.w, b2.w, acc);
        acc = fmaf(a3.x * w3.x, b3.x, acc);
        acc = fmaf(a3.y * w3.y, b3.y, acc);
        acc = fmaf(a3.z * w3.z, b3.z, acc);
        acc = fmaf(a3.w * w3.w, b3.w, acc);

        // Reduce across the 8-lane group.
        acc += __shfl_xor_sync(0xFFFFFFFFu, acc, 4);
        acc += __shfl_xor_sync(0xFFFFFFFFu, acc, 2);
        acc += __shfl_xor_sync(0xFFFFFFFFu, acc, 1);

        if (sub == 0)
            outR[e0 + i * STRIDE] = 1.0f / (1.0f + __expf(-acc));
    }
}

extern "C" void kernel_launch(void* const* d_in, const int* in_sizes, int n_in,
                              void* d_out, int out_size) {
    const float4* h4 = (const float4*)d_in[0];
    const float4* W4 = (const float4*)d_in[1];
    const int*   src = (const int*)d_in[2];
    const int*   dst = (const int*)d_in[3];
    float* out = (float*)d_out;

    dim3 grid(GRID_X, N_REL);
    distmult_kernel<<<grid, BLOCK>>>(h4, W4, src, dst, out);
}